// round 4
// baseline (speedup 1.0000x reference)
#include <cuda_runtime.h>

#define FULL 0xFFFFFFFFu

// Problem constants
#define BATCH 32
#define IN    2048
#define OUT   2048
#define KNUM  8
#define HDIM  512
#define KSZ   (IN * OUT)          // 4M elements per expert

#define IBLK   256                // i-range per main block
#define NCHUNK (IN / IBLK)        // 8
#define OBLK   32                 // o's per block (4 warps x 8 o)
#define NOBLK  (OUT / OBLK)       // 64
#define XSTR   260                // x_s row stride, 4*odd -> LDS.128 conflict-free

// Scratch (device globals; fully overwritten every call -> graph-replay safe)
__device__ float g_h_partial[64 * HDIM];
__device__ float g_alpha[KNUM];

// ---------------------------------------------------------------------------
// K0a: partials of h = cond @ w1 (64 blocks x 512 thr, 32 rows each)
//      + zero `out` for the atomic accumulation in main.
// ---------------------------------------------------------------------------
__global__ void mlp1_kernel(const float* __restrict__ cond,
                            const float* __restrict__ w1,
                            float* __restrict__ out) {
    int j  = threadIdx.x;         // 0..511
    int p  = blockIdx.x;          // 0..63
    int i0 = p * 32;
    float s = 0.f;
#pragma unroll
    for (int i = 0; i < 32; ++i)
        s += cond[i0 + i] * w1[(i0 + i) * HDIM + j];
    g_h_partial[p * HDIM + j] = s;

    // zero out: 32768 threads x float2 = 65536 floats
    reinterpret_cast<float2*>(out)[p * 512 + j] = make_float2(0.f, 0.f);
}

// ---------------------------------------------------------------------------
// K0b: reduce partials, relu, scores = h @ w2 + b2, softmax -> g_alpha
// ---------------------------------------------------------------------------
__global__ void mlp2_kernel(const float* __restrict__ b1,
                            const float* __restrict__ w2,
                            const float* __restrict__ b2) {
    __shared__ float h_s[HDIM];
    __shared__ float s_s[KNUM];
    int j = threadIdx.x;          // 512 threads
    float h = b1[j];
#pragma unroll 8
    for (int p = 0; p < 64; ++p) h += g_h_partial[p * HDIM + j];
    h_s[j] = fmaxf(h, 0.f);
    __syncthreads();

    int wid = j >> 5, lane = j & 31;
    if (wid < KNUM) {
        float s = 0.f;
#pragma unroll
        for (int m = 0; m < HDIM / 32; ++m) {
            int jj = lane + m * 32;
            s += h_s[jj] * w2[jj * KNUM + wid];
        }
#pragma unroll
        for (int off = 16; off; off >>= 1) s += __shfl_xor_sync(FULL, s, off);
        if (lane == 0) s_s[wid] = s + b2[wid];
    }
    __syncthreads();
    if (j == 0) {
        float mx = -1e30f;
#pragma unroll
        for (int k = 0; k < KNUM; ++k) mx = fmaxf(mx, s_s[k]);
        float e[KNUM];
        float sum = 0.f;
#pragma unroll
        for (int k = 0; k < KNUM; ++k) { e[k] = __expf(s_s[k] - mx); sum += e[k]; }
        float inv = 1.f / sum;
#pragma unroll
        for (int k = 0; k < KNUM; ++k) g_alpha[k] = e[k] * inv;
    }
}

// ---------------------------------------------------------------------------
// Main: out[b,o] (+)= sum_{i in chunk} (sum_k a_k KW[k,o,i]) * x[b,i]
//       (+ aggregated bias from the c==0 blocks)
// grid = NCHUNK*NOBLK = 512 blocks x 128 threads (4 warps, 8 o per warp).
// Compute layout: lane = (og = lane>>5? no: lane>>4, bl = lane&15);
//   each lane computes 4 o (o-group og) x 2 b (bl, bl+16) x 4 i per iter.
// Per iter: 2 x LDS.128 + 4 w LDS.128 -> 32 FFMA.
// ---------------------------------------------------------------------------
__global__ __launch_bounds__(128) void main_kernel(
        const float* __restrict__ x,    // [32, 2048]
        const float* __restrict__ kw,   // [8, 2048, 2048]
        const float* __restrict__ kb,   // [8, 2048]
        float* __restrict__ out) {      // [32, 2048]
    extern __shared__ float sm[];
    float* x_s   = sm;                          // 32 * 260      = 8320
    float* w_s   = sm + BATCH * XSTR;           // 32 o * 128 i  = 4096
    float* out_s = w_s + OBLK * 128;            // 32 * 33       = 1056
    float* a_s   = out_s + 32 * 33;             // 8

    int t    = threadIdx.x;
    int wid  = t >> 5;
    int lane = t & 31;
    int ob   = blockIdx.x & (NOBLK - 1);        // 0..63
    int c    = blockIdx.x >> 6;                 // 0..7
    int i0   = c * IBLK;
    int o_base = ob * OBLK + wid * 8;           // this warp's first o

    if (t < KNUM) a_s[t] = g_alpha[t];

    // stage x tile: x_s[b][il], float4, stride 260 (4*65 -> conflict-free)
    const float4* x4 = reinterpret_cast<const float4*>(x);
#pragma unroll
    for (int jj = 0; jj < (BATCH * IBLK) / (4 * 128); ++jj) {
        int idx = jj * 128 + t;                 // 0..2047 float4 units
        int b   = idx >> 6;
        int il4 = idx & 63;
        *reinterpret_cast<float4*>(&x_s[b * XSTR + il4 * 4]) =
            x4[(b * IN + i0) / 4 + il4];
    }
    __syncthreads();

    float a[KNUM];
#pragma unroll
    for (int k = 0; k < KNUM; ++k) a[k] = a_s[k];

    int bl = lane & 15;
    int og = lane >> 4;

    float4 acc[4][2];
#pragma unroll
    for (int oo = 0; oo < 4; ++oo)
#pragma unroll
        for (int bh = 0; bh < 2; ++bh)
            acc[oo][bh] = make_float4(0.f, 0.f, 0.f, 0.f);

#pragma unroll
    for (int h = 0; h < 2; ++h) {
        // ---- aggregation: w_s[o_local][i] = sum_k a_k kw[k][o][i-range] ----
        // lanes cover the 128-i half: lane*4 .. lane*4+3
        const float* base = kw + (size_t)o_base * IN + i0 + h * 128 + lane * 4;
#pragma unroll
        for (int g = 0; g < 2; ++g) {           // two 4-o groups
            float4 cur[4], wa[4];
#pragma unroll
            for (int oo = 0; oo < 4; ++oo)
                cur[oo] = *reinterpret_cast<const float4*>(
                              base + (size_t)(g * 4 + oo) * IN);
            // software pipeline over k: load k+1 while FMA k
#pragma unroll
            for (int k = 0; k < KNUM; ++k) {
                float4 nxt[4];
                if (k < KNUM - 1) {
#pragma unroll
                    for (int oo = 0; oo < 4; ++oo)
                        nxt[oo] = *reinterpret_cast<const float4*>(
                                      base + (size_t)(k + 1) * KSZ +
                                      (size_t)(g * 4 + oo) * IN);
                }
                float ak = a[k];
#pragma unroll
                for (int oo = 0; oo < 4; ++oo) {
                    if (k == 0) {
                        wa[oo].x = ak * cur[oo].x; wa[oo].y = ak * cur[oo].y;
                        wa[oo].z = ak * cur[oo].z; wa[oo].w = ak * cur[oo].w;
                    } else {
                        wa[oo].x += ak * cur[oo].x; wa[oo].y += ak * cur[oo].y;
                        wa[oo].z += ak * cur[oo].z; wa[oo].w += ak * cur[oo].w;
                    }
                }
#pragma unroll
                for (int oo = 0; oo < 4; ++oo) cur[oo] = nxt[oo];
            }
#pragma unroll
            for (int oo = 0; oo < 4; ++oo)
                *reinterpret_cast<float4*>(
                    &w_s[(wid * 8 + g * 4 + oo) * 128 + lane * 4]) = wa[oo];
        }
        __syncwarp();

        // ---- compute: 32 iters x (2 x-loads + 4 w-loads + 32 FFMA) ----
#pragma unroll 8
        for (int src = 0; src < 32; ++src) {
            float4 x0 = *reinterpret_cast<const float4*>(
                            &x_s[bl * XSTR + h * 128 + src * 4]);
            float4 x1 = *reinterpret_cast<const float4*>(
                            &x_s[(bl + 16) * XSTR + h * 128 + src * 4]);
#pragma unroll
            for (int oo = 0; oo < 4; ++oo) {
                float4 wq = *reinterpret_cast<const float4*>(
                                &w_s[(wid * 8 + og * 4 + oo) * 128 + src * 4]);
                acc[oo][0].x += wq.x * x0.x; acc[oo][0].y += wq.y * x0.y;
                acc[oo][0].z += wq.z * x0.z; acc[oo][0].w += wq.w * x0.w;
                acc[oo][1].x += wq.x * x1.x; acc[oo][1].y += wq.y * x1.y;
                acc[oo][1].z += wq.z * x1.z; acc[oo][1].w += wq.w * x1.w;
            }
        }
        __syncwarp();   // before w_s overwrite next half
    }

    // ---- epilogue: bias (c==0 only), transpose, atomic add ----
    float bb[4] = {0.f, 0.f, 0.f, 0.f};
    if (c == 0) {
#pragma unroll
        for (int oo = 0; oo < 4; ++oo) {
            int o = o_base + og * 4 + oo;
            float s = 0.f;
#pragma unroll
            for (int k = 0; k < KNUM; ++k) s += a[k] * kb[k * OUT + o];
            bb[oo] = s;
        }
    }
#pragma unroll
    for (int oo = 0; oo < 4; ++oo)
#pragma unroll
        for (int bh = 0; bh < 2; ++bh) {
            float v = (acc[oo][bh].x + acc[oo][bh].y) +
                      (acc[oo][bh].z + acc[oo][bh].w) + bb[oo];
            out_s[(bl + bh * 16) * 33 + (wid * 8 + og * 4 + oo)] = v;
        }
    __syncthreads();

    // 128 threads x 8 elements each: coalesced-ish REDG.ADD
    {
        int b   = t >> 2;              // 0..31
        int ol0 = (t & 3) * 8;         // 0,8,16,24
#pragma unroll
        for (int jj = 0; jj < 8; ++jj)
            atomicAdd(&out[b * OUT + ob * OBLK + ol0 + jj],
                      out_s[b * 33 + ol0 + jj]);
    }
}

// ---------------------------------------------------------------------------
extern "C" void kernel_launch(void* const* d_in, const int* in_sizes, int n_in,
                              void* d_out, int out_size) {
    const float* x    = (const float*)d_in[0];
    const float* cond = (const float*)d_in[1];
    const float* w1   = (const float*)d_in[2];
    const float* b1   = (const float*)d_in[3];
    const float* w2   = (const float*)d_in[4];
    const float* b2   = (const float*)d_in[5];
    const float* kw   = (const float*)d_in[6];
    const float* kb   = (const float*)d_in[7];
    float* out = (float*)d_out;

    static int smem_set = 0;
    const int SMEM_MAIN = (BATCH * XSTR + OBLK * 128 + 32 * 33 + 8) * 4;
    if (!smem_set) {
        cudaFuncSetAttribute(main_kernel,
                             cudaFuncAttributeMaxDynamicSharedMemorySize,
                             SMEM_MAIN);
        smem_set = 1;
    }

    mlp1_kernel<<<64, HDIM>>>(cond, w1, out);
    mlp2_kernel<<<1, HDIM>>>(b1, w2, b2);
    main_kernel<<<NCHUNK * NOBLK, 128, SMEM_MAIN>>>(x, kw, kb, out);
}

// round 5
// speedup vs baseline: 1.0558x; 1.0558x over previous
#include <cuda_runtime.h>

#define FULL 0xFFFFFFFFu

// Problem constants
#define BATCH 32
#define IN    2048
#define OUT   2048
#define KNUM  8
#define HDIM  512
#define KSZ   (IN * OUT)          // 4M elements per expert

#define IBLK   256                // i-range per main block
#define NCHUNK (IN / IBLK)        // 8
#define OBLK   32                 // o's per block (4 warps x 8 o)
#define NOBLK  (OUT / OBLK)       // 64
#define XSTL   33                 // x_s stride (transposed [i][b])
#define WSTR   132                // w_s row stride (132%32=4; og rows 528 apart -> +16 banks)

// Scratch (device globals; fully overwritten every call -> graph-replay safe)
__device__ float g_h_partial[128 * HDIM];
__device__ float g_alpha[KNUM];

// ---------------------------------------------------------------------------
// K0a: partials of h = cond @ w1 (128 blocks x 512 thr, 16 rows each)
//      + zero `out` (128*512 threads x 1 float = 65536 = BATCH*OUT).
// ---------------------------------------------------------------------------
__global__ void mlp1_kernel(const float* __restrict__ cond,
                            const float* __restrict__ w1,
                            float* __restrict__ out) {
    int j  = threadIdx.x;         // 0..511
    int p  = blockIdx.x;          // 0..127
    int i0 = p * 16;
    float s0 = 0.f, s1 = 0.f;
#pragma unroll
    for (int i = 0; i < 16; i += 2) {
        s0 += cond[i0 + i]     * w1[(i0 + i) * HDIM + j];
        s1 += cond[i0 + i + 1] * w1[(i0 + i + 1) * HDIM + j];
    }
    g_h_partial[p * HDIM + j] = s0 + s1;
    out[p * HDIM + j] = 0.f;
}

// ---------------------------------------------------------------------------
// K0b: reduce partials, relu, scores = h @ w2 + b2, softmax -> g_alpha
// ---------------------------------------------------------------------------
__global__ void mlp2_kernel(const float* __restrict__ b1,
                            const float* __restrict__ w2,
                            const float* __restrict__ b2) {
    __shared__ float h_s[HDIM];
    __shared__ float s_s[KNUM];
    int j = threadIdx.x;          // 512 threads
    float h0 = 0.f, h1 = 0.f, h2 = 0.f, h3 = 0.f;
#pragma unroll 4
    for (int p = 0; p < 128; p += 4) {
        h0 += g_h_partial[(p + 0) * HDIM + j];
        h1 += g_h_partial[(p + 1) * HDIM + j];
        h2 += g_h_partial[(p + 2) * HDIM + j];
        h3 += g_h_partial[(p + 3) * HDIM + j];
    }
    h_s[j] = fmaxf((h0 + h1) + (h2 + h3) + b1[j], 0.f);
    __syncthreads();

    int wid = j >> 5, lane = j & 31;
    if (wid < KNUM) {
        float s = 0.f;
#pragma unroll
        for (int m = 0; m < HDIM / 32; ++m) {
            int jj = lane + m * 32;
            s += h_s[jj] * w2[jj * KNUM + wid];
        }
#pragma unroll
        for (int off = 16; off; off >>= 1) s += __shfl_xor_sync(FULL, s, off);
        if (lane == 0) s_s[wid] = s + b2[wid];
    }
    __syncthreads();
    if (j == 0) {
        float mx = -1e30f;
#pragma unroll
        for (int k = 0; k < KNUM; ++k) mx = fmaxf(mx, s_s[k]);
        float e[KNUM];
        float sum = 0.f;
#pragma unroll
        for (int k = 0; k < KNUM; ++k) { e[k] = __expf(s_s[k] - mx); sum += e[k]; }
        float inv = 1.f / sum;
#pragma unroll
        for (int k = 0; k < KNUM; ++k) g_alpha[k] = e[k] * inv;
    }
}

// ---------------------------------------------------------------------------
// Main: out[b,o] (+)= sum_{i in chunk} (sum_k a_k KW[k,o,i]) * x[b,i]
//       (+ aggregated bias from the c==0 blocks)
// grid = 512 blocks x 128 threads (4 warps x 8 o). lane = (og=lane>>4, bl=lane&15).
// Each lane: 4 o (group og) x 2 b (bl, bl+16) x 4 i per iter.
// Per iter: 8 scalar x-LDS (conflict-free) + 4 w-LDS.128 (bank-split) -> 32 FFMA.
// ---------------------------------------------------------------------------
__global__ __launch_bounds__(128, 4) void main_kernel(
        const float* __restrict__ x,    // [32, 2048]
        const float* __restrict__ kw,   // [8, 2048, 2048]
        const float* __restrict__ kb,   // [8, 2048]
        float* __restrict__ out) {      // [32, 2048]
    extern __shared__ float sm[];
    float* x_s   = sm;                           // 256*33 = 8448 (transposed [i][b])
    float* w_s   = sm + IBLK * XSTL;             // 32*132 = 4224
    float* out_s = w_s + OBLK * WSTR;            // 32*33  = 1056
    float* a_s   = out_s + 32 * 33;              // 8

    int t    = threadIdx.x;
    int wid  = t >> 5;
    int lane = t & 31;
    int ob   = blockIdx.x & (NOBLK - 1);         // 0..63
    int c    = blockIdx.x >> 6;                  // 0..7
    int i0   = c * IBLK;
    int o_base = ob * OBLK + wid * 8;

    if (t < KNUM) a_s[t] = g_alpha[t];

    // stage x transposed: x_s[il][b] = x[b][i0+il]; global float4, smem scatter
    const float4* x4 = reinterpret_cast<const float4*>(x);
#pragma unroll
    for (int jj = 0; jj < (BATCH * IBLK) / (4 * 128); ++jj) {
        int idx = jj * 128 + t;                  // 0..2047 float4 units
        int b   = idx >> 6;                      // 64 float4 per row
        int il4 = idx & 63;
        float4 v = x4[(b * IN + i0) / 4 + il4];
        x_s[(il4 * 4 + 0) * XSTL + b] = v.x;
        x_s[(il4 * 4 + 1) * XSTL + b] = v.y;
        x_s[(il4 * 4 + 2) * XSTL + b] = v.z;
        x_s[(il4 * 4 + 3) * XSTL + b] = v.w;
    }
    __syncthreads();

    float a[KNUM];
#pragma unroll
    for (int k = 0; k < KNUM; ++k) a[k] = a_s[k];

    int bl = lane & 15;
    int og = lane >> 4;

    float4 acc[4][2];
#pragma unroll
    for (int oo = 0; oo < 4; ++oo)
#pragma unroll
        for (int bh = 0; bh < 2; ++bh)
            acc[oo][bh] = make_float4(0.f, 0.f, 0.f, 0.f);

#pragma unroll
    for (int h = 0; h < 2; ++h) {
        // ---- aggregation: w_s[o_local][i] = sum_k a_k kw[k][o][...] ----
        const float* wbase = kw + (size_t)o_base * IN + i0 + h * 128 + lane * 4;
#pragma unroll 2
        for (int oo = 0; oo < 8; ++oo) {
            const float* p = wbase + (size_t)oo * IN;
            float4 v0 = *reinterpret_cast<const float4*>(p);
            float4 v1 = *reinterpret_cast<const float4*>(p + 1ul * KSZ);
            float4 v2 = *reinterpret_cast<const float4*>(p + 2ul * KSZ);
            float4 v3 = *reinterpret_cast<const float4*>(p + 3ul * KSZ);
            float4 v4 = *reinterpret_cast<const float4*>(p + 4ul * KSZ);
            float4 v5 = *reinterpret_cast<const float4*>(p + 5ul * KSZ);
            float4 v6 = *reinterpret_cast<const float4*>(p + 6ul * KSZ);
            float4 v7 = *reinterpret_cast<const float4*>(p + 7ul * KSZ);
            float4 w;
            w.x = ((a[0]*v0.x + a[1]*v1.x) + (a[2]*v2.x + a[3]*v3.x)) +
                  ((a[4]*v4.x + a[5]*v5.x) + (a[6]*v6.x + a[7]*v7.x));
            w.y = ((a[0]*v0.y + a[1]*v1.y) + (a[2]*v2.y + a[3]*v3.y)) +
                  ((a[4]*v4.y + a[5]*v5.y) + (a[6]*v6.y + a[7]*v7.y));
            w.z = ((a[0]*v0.z + a[1]*v1.z) + (a[2]*v2.z + a[3]*v3.z)) +
                  ((a[4]*v4.z + a[5]*v5.z) + (a[6]*v6.z + a[7]*v7.z));
            w.w = ((a[0]*v0.w + a[1]*v1.w) + (a[2]*v2.w + a[3]*v3.w)) +
                  ((a[4]*v4.w + a[5]*v5.w) + (a[6]*v6.w + a[7]*v7.w));
            *reinterpret_cast<float4*>(
                &w_s[(wid * 8 + oo) * WSTR + lane * 4]) = w;
        }
        __syncwarp();

        // ---- compute: 32 iters x (8 x-LDS + 4 w-LDS.128 + 32 FFMA) ----
#pragma unroll 8
        for (int src = 0; src < 32; ++src) {
            int ibase = h * 128 + src * 4;
            float xa[4], xb[4];
#pragma unroll
            for (int jx = 0; jx < 4; ++jx) {
                xa[jx] = x_s[(ibase + jx) * XSTL + bl];
                xb[jx] = x_s[(ibase + jx) * XSTL + bl + 16];
            }
#pragma unroll
            for (int oo = 0; oo < 4; ++oo) {
                float4 wq = *reinterpret_cast<const float4*>(
                    &w_s[(wid * 8 + og * 4 + oo) * WSTR + src * 4]);
                acc[oo][0].x += wq.x * xa[0]; acc[oo][0].y += wq.y * xa[1];
                acc[oo][0].z += wq.z * xa[2]; acc[oo][0].w += wq.w * xa[3];
                acc[oo][1].x += wq.x * xb[0]; acc[oo][1].y += wq.y * xb[1];
                acc[oo][1].z += wq.z * xb[2]; acc[oo][1].w += wq.w * xb[3];
            }
        }
        __syncwarp();   // before w_s overwrite next half
    }

    // ---- epilogue: bias (c==0 only), transpose, atomic add ----
    float bb[4] = {0.f, 0.f, 0.f, 0.f};
    if (c == 0) {
#pragma unroll
        for (int oo = 0; oo < 4; ++oo) {
            int o = o_base + og * 4 + oo;
            float s = 0.f;
#pragma unroll
            for (int k = 0; k < KNUM; ++k) s += a[k] * kb[k * OUT + o];
            bb[oo] = s;
        }
    }
#pragma unroll
    for (int oo = 0; oo < 4; ++oo)
#pragma unroll
        for (int bh = 0; bh < 2; ++bh) {
            float v = (acc[oo][bh].x + acc[oo][bh].y) +
                      (acc[oo][bh].z + acc[oo][bh].w) + bb[oo];
            out_s[(bl + bh * 16) * 33 + (wid * 8 + og * 4 + oo)] = v;
        }
    __syncthreads();

    {
        int b   = t >> 2;              // 0..31
        int ol0 = (t & 3) * 8;         // 0,8,16,24
#pragma unroll
        for (int jj = 0; jj < 8; ++jj)
            atomicAdd(&out[b * OUT + ob * OBLK + ol0 + jj],
                      out_s[b * 33 + ol0 + jj]);
    }
}

// ---------------------------------------------------------------------------
extern "C" void kernel_launch(void* const* d_in, const int* in_sizes, int n_in,
                              void* d_out, int out_size) {
    const float* x    = (const float*)d_in[0];
    const float* cond = (const float*)d_in[1];
    const float* w1   = (const float*)d_in[2];
    const float* b1   = (const float*)d_in[3];
    const float* w2   = (const float*)d_in[4];
    const float* b2   = (const float*)d_in[5];
    const float* kw   = (const float*)d_in[6];
    const float* kb   = (const float*)d_in[7];
    float* out = (float*)d_out;

    const int SMEM_MAIN = (IBLK * XSTL + OBLK * WSTR + 32 * 33 + 8) * 4;
    static int smem_set = 0;
    if (!smem_set) {
        cudaFuncSetAttribute(main_kernel,
                             cudaFuncAttributeMaxDynamicSharedMemorySize,
                             SMEM_MAIN);
        smem_set = 1;
    }

    mlp1_kernel<<<128, HDIM>>>(cond, w1, out);
    mlp2_kernel<<<1, HDIM>>>(b1, w2, b2);
    main_kernel<<<NCHUNK * NOBLK, 128, SMEM_MAIN>>>(x, kw, kb, out);
}

// round 6
// speedup vs baseline: 1.1151x; 1.0561x over previous
#include <cuda_runtime.h>

#define FULL 0xFFFFFFFFu

// Problem constants
#define BATCH 32
#define IN    2048
#define OUT   2048
#define KNUM  8
#define HDIM  512
#define KSZ   (IN * OUT)          // 4M elements per expert

#define IBLK   512                // i-range per main block (4 x 128 halves)
#define NCHUNK (IN / IBLK)        // 4
#define OBLK   16                 // o's per block (8 warps x 2 o)
#define NOBLK  (OUT / OBLK)       // 128
#define XSTR   516                // x_s row stride: 516%32==4 -> even bank spread

// Scratch (device globals; fully overwritten every call -> graph-replay safe)
__device__ float g_h_partial[128 * HDIM];
__device__ float g_alpha[KNUM];

// ---------------------------------------------------------------------------
// K0a: partials of h = cond @ w1 (128 blocks x 512 thr, 16 rows each)
// ---------------------------------------------------------------------------
__global__ void mlp1_kernel(const float* __restrict__ cond,
                            const float* __restrict__ w1) {
    int j  = threadIdx.x;         // 0..511
    int p  = blockIdx.x;          // 0..127
    int i0 = p * 16;
    float s0 = 0.f, s1 = 0.f;
#pragma unroll
    for (int i = 0; i < 16; i += 2) {
        s0 += cond[i0 + i]     * w1[(i0 + i) * HDIM + j];
        s1 += cond[i0 + i + 1] * w1[(i0 + i + 1) * HDIM + j];
    }
    g_h_partial[p * HDIM + j] = s0 + s1;
}

// ---------------------------------------------------------------------------
// K0b: reduce partials (float4, 4-way p-split), relu, scores, softmax
// ---------------------------------------------------------------------------
__global__ void mlp2_kernel(const float* __restrict__ b1,
                            const float* __restrict__ w2,
                            const float* __restrict__ b2) {
    __shared__ float4 hq_s[4][HDIM / 4];
    __shared__ float  h_s[HDIM];
    __shared__ float  s_s[KNUM];
    int t = threadIdx.x;          // 512 threads
    int q  = t >> 7;              // p-quarter 0..3
    int j4 = t & 127;             // float4 index over HDIM

    const float4* hp4 = reinterpret_cast<const float4*>(g_h_partial);
    float4 s = make_float4(0.f, 0.f, 0.f, 0.f);
#pragma unroll
    for (int p = 0; p < 32; ++p) {
        float4 v = hp4[(q * 32 + p) * (HDIM / 4) + j4];
        s.x += v.x; s.y += v.y; s.z += v.z; s.w += v.w;
    }
    hq_s[q][j4] = s;
    __syncthreads();

    if (t < HDIM / 4) {
        float4 v0 = hq_s[0][t], v1 = hq_s[1][t],
               v2 = hq_s[2][t], v3 = hq_s[3][t];
        const float4* b14 = reinterpret_cast<const float4*>(b1);
        float4 bb = b14[t];
        h_s[t * 4 + 0] = fmaxf((v0.x + v1.x) + (v2.x + v3.x) + bb.x, 0.f);
        h_s[t * 4 + 1] = fmaxf((v0.y + v1.y) + (v2.y + v3.y) + bb.y, 0.f);
        h_s[t * 4 + 2] = fmaxf((v0.z + v1.z) + (v2.z + v3.z) + bb.z, 0.f);
        h_s[t * 4 + 3] = fmaxf((v0.w + v1.w) + (v2.w + v3.w) + bb.w, 0.f);
    }
    __syncthreads();

    int wid = t >> 5, lane = t & 31;
    if (wid < KNUM) {
        float sc = 0.f;
#pragma unroll
        for (int m = 0; m < HDIM / 32; ++m) {
            int jj = lane + m * 32;
            sc += h_s[jj] * w2[jj * KNUM + wid];
        }
#pragma unroll
        for (int off = 16; off; off >>= 1) sc += __shfl_xor_sync(FULL, sc, off);
        if (lane == 0) s_s[wid] = sc + b2[wid];
    }
    __syncthreads();
    if (t == 0) {
        float mx = -1e30f;
#pragma unroll
        for (int k = 0; k < KNUM; ++k) mx = fmaxf(mx, s_s[k]);
        float e[KNUM];
        float sum = 0.f;
#pragma unroll
        for (int k = 0; k < KNUM; ++k) { e[k] = __expf(s_s[k] - mx); sum += e[k]; }
        float inv = 1.f / sum;
#pragma unroll
        for (int k = 0; k < KNUM; ++k) g_alpha[k] = e[k] * inv;
    }
}

// ---------------------------------------------------------------------------
// K0c: zero `out` (also shifts main to global launch #4 for ncu)
// ---------------------------------------------------------------------------
__global__ void zero_out_kernel(float* __restrict__ out) {
    int idx = blockIdx.x * 256 + threadIdx.x;   // 0..16383 (float4 units)
    reinterpret_cast<float4*>(out)[idx] = make_float4(0.f, 0.f, 0.f, 0.f);
}

// ---------------------------------------------------------------------------
// Main: out[b,o] (+)= sum_{i in chunk} (sum_k a_k KW[k,o,i]) * x[b,i]
// grid = NCHUNK*NOBLK = 512 blocks x 256 threads (8 warps x 2 o).
// Steady-state pipeline over 4 x 128-i halves:
//   agg cur -> w regs; reload cur in place for next half (16 LDG.128 in
//   flight during compute); STS w; 32-iter compute (1 x-LDS.128 +
//   2 w-broadcast-LDS.128 + 8 FFMA per iter). lane = batch row b.
// ---------------------------------------------------------------------------
__global__ __launch_bounds__(256, 2) void main_kernel(
        const float* __restrict__ x,    // [32, 2048]
        const float* __restrict__ kw,   // [8, 2048, 2048]
        const float* __restrict__ kb,   // [8, 2048]
        float* __restrict__ out) {      // [32, 2048]
    extern __shared__ float sm[];
    float* x_s   = sm;                            // 32 * 516 = 16512 floats
    float* w_s   = sm + BATCH * XSTR;             // 8 warps * 2 * 128 = 2048
    float* out_s = w_s + 8 * 2 * 128;             // 32 * 17 = 544
    float* a_s   = out_s + 32 * 17;               // 8

    int t    = threadIdx.x;
    int wid  = t >> 5;
    int lane = t & 31;
    int ob   = blockIdx.x & (NOBLK - 1);          // 0..127
    int c    = blockIdx.x >> 7;                   // 0..3
    int i0   = c * IBLK;
    int o0   = ob * OBLK + wid;                   // warp's o pair: o0, o0+8
    int o1   = o0 + 8;

    if (t < KNUM) a_s[t] = g_alpha[t];

    // issue first half's cur loads BEFORE x staging (staging hides latency)
    const float* base0 = kw + (size_t)o0 * IN + i0 + lane * 4;
    const float* base1 = kw + (size_t)o1 * IN + i0 + lane * 4;
    float4 cur0[KNUM], cur1[KNUM];
#pragma unroll
    for (int k = 0; k < KNUM; ++k) {
        cur0[k] = *reinterpret_cast<const float4*>(base0 + (size_t)k * KSZ);
        cur1[k] = *reinterpret_cast<const float4*>(base1 + (size_t)k * KSZ);
    }

    // stage x tile: x_s[b][il] = x[b][i0+il], float4
    const float4* x4 = reinterpret_cast<const float4*>(x);
#pragma unroll
    for (int jj = 0; jj < (BATCH * IBLK) / (4 * 256); ++jj) {
        int idx = jj * 256 + t;                   // 0..4095 float4 units
        int b   = idx >> 7;                       // 128 f4 per row
        int il4 = idx & 127;
        *reinterpret_cast<float4*>(&x_s[b * XSTR + il4 * 4]) =
            x4[(b * IN + i0) / 4 + il4];
    }
    __syncthreads();

    float a[KNUM];
#pragma unroll
    for (int k = 0; k < KNUM; ++k) a[k] = a_s[k];

    float4 acc0 = make_float4(0.f, 0.f, 0.f, 0.f);
    float4 acc1 = make_float4(0.f, 0.f, 0.f, 0.f);

#pragma unroll
    for (int h = 0; h < IBLK / 128; ++h) {
        // ---- aggregate experts (consumes cur) ----
        float4 w40 = make_float4(0.f, 0.f, 0.f, 0.f);
        float4 w41 = make_float4(0.f, 0.f, 0.f, 0.f);
#pragma unroll
        for (int k = 0; k < KNUM; ++k) {
            float ak = a[k];
            w40.x += ak * cur0[k].x; w40.y += ak * cur0[k].y;
            w40.z += ak * cur0[k].z; w40.w += ak * cur0[k].w;
            w41.x += ak * cur1[k].x; w41.y += ak * cur1[k].y;
            w41.z += ak * cur1[k].z; w41.w += ak * cur1[k].w;
        }

        // ---- reload cur in place for next half (hidden under compute) ----
        if (h < IBLK / 128 - 1) {
            int off = (h + 1) * 128;
#pragma unroll
            for (int k = 0; k < KNUM; ++k) {
                cur0[k] = *reinterpret_cast<const float4*>(
                              base0 + (size_t)k * KSZ + off);
                cur1[k] = *reinterpret_cast<const float4*>(
                              base1 + (size_t)k * KSZ + off);
            }
        }

        // ---- stage aggregated strips (warp-private rows) ----
        *reinterpret_cast<float4*>(&w_s[(wid * 2 + 0) * 128 + lane * 4]) = w40;
        *reinterpret_cast<float4*>(&w_s[(wid * 2 + 1) * 128 + lane * 4]) = w41;
        __syncwarp();

        // ---- compute: lane = b; 4 i per iter ----
#pragma unroll 8
        for (int src = 0; src < 32; ++src) {
            float4 xq  = *reinterpret_cast<const float4*>(
                             &x_s[lane * XSTR + h * 128 + src * 4]);
            float4 wq0 = *reinterpret_cast<const float4*>(
                             &w_s[(wid * 2 + 0) * 128 + src * 4]);
            float4 wq1 = *reinterpret_cast<const float4*>(
                             &w_s[(wid * 2 + 1) * 128 + src * 4]);
            acc0.x += wq0.x * xq.x; acc0.y += wq0.y * xq.y;
            acc0.z += wq0.z * xq.z; acc0.w += wq0.w * xq.w;
            acc1.x += wq1.x * xq.x; acc1.y += wq1.y * xq.y;
            acc1.z += wq1.z * xq.z; acc1.w += wq1.w * xq.w;
        }
        __syncwarp();   // before w_s overwrite next half
    }

    // ---- epilogue: bias (c==0 only), transpose, atomic add ----
    float bb0 = 0.f, bb1 = 0.f;
    if (c == 0) {
#pragma unroll
        for (int k = 0; k < KNUM; ++k) {
            bb0 += a[k] * kb[k * OUT + o0];
            bb1 += a[k] * kb[k * OUT + o1];
        }
    }
    float v0 = (acc0.x + acc0.y) + (acc0.z + acc0.w) + bb0;
    float v1 = (acc1.x + acc1.y) + (acc1.z + acc1.w) + bb1;

    __syncthreads();
    out_s[lane * 17 + wid]     = v0;   // lane = b
    out_s[lane * 17 + wid + 8] = v1;
    __syncthreads();
#pragma unroll
    for (int r = 0; r < 2; ++r) {
        int idx = r * 256 + t;                    // 0..511
        int b   = idx >> 4;
        int oi  = idx & 15;
        atomicAdd(&out[b * OUT + ob * OBLK + oi], out_s[b * 17 + oi]);
    }
}

// ---------------------------------------------------------------------------
extern "C" void kernel_launch(void* const* d_in, const int* in_sizes, int n_in,
                              void* d_out, int out_size) {
    const float* x    = (const float*)d_in[0];
    const float* cond = (const float*)d_in[1];
    const float* w1   = (const float*)d_in[2];
    const float* b1   = (const float*)d_in[3];
    const float* w2   = (const float*)d_in[4];
    const float* b2   = (const float*)d_in[5];
    const float* kw   = (const float*)d_in[6];
    const float* kb   = (const float*)d_in[7];
    float* out = (float*)d_out;

    const int SMEM_MAIN = (BATCH * XSTR + 8 * 2 * 128 + 32 * 17 + 8) * 4;
    static int smem_set = 0;
    if (!smem_set) {
        cudaFuncSetAttribute(main_kernel,
                             cudaFuncAttributeMaxDynamicSharedMemorySize,
                             SMEM_MAIN);
        smem_set = 1;
    }

    mlp1_kernel<<<128, HDIM>>>(cond, w1);
    mlp2_kernel<<<1, HDIM>>>(b1, w2, b2);
    zero_out_kernel<<<(BATCH * OUT) / (4 * 256), 256>>>(out);
    main_kernel<<<NCHUNK * NOBLK, 256, SMEM_MAIN>>>(x, kw, kb, out);
}